// round 1
// baseline (speedup 1.0000x reference)
#include <cuda_runtime.h>

// Problem constants
#define BATCH 2
#define SEQ   2048
#define HID   2048
#define NHEAD 16
#define HDIM  128
#define MROWS (BATCH * SEQ)   // 4096
#define K3    (3 * HID)       // 6144

// Scratch (allocation-free rule: __device__ globals)
__device__ float g_qkv[(size_t)MROWS * K3];  // [4096, 6144] ~100 MB
__device__ float g_ctx[(size_t)MROWS * HID]; // [4096, 2048] ~33 MB

// ---------------------------------------------------------------------------
// SGEMM: C[M,N] = A[M,K] @ B[K,N] + bias[N]
// BM=BN=128, BK=16, 256 threads, 8x8 per thread. M,N,K multiples of 128/16.
// ---------------------------------------------------------------------------
__global__ __launch_bounds__(256, 2)
void sgemm_bias_kernel(const float* __restrict__ A, const float* __restrict__ Bw,
                       const float* __restrict__ bias, float* __restrict__ C,
                       int N, int K) {
    __shared__ float As[16][128];  // transposed A tile
    __shared__ float Bs[16][128];

    const int tid = threadIdx.x;
    const int tx = tid & 15;
    const int ty = tid >> 4;
    const int bx = blockIdx.x, by = blockIdx.y;

    const float* Ablk = A + (size_t)(by * 128) * K;
    const float* Bblk = Bw + bx * 128;

    float acc[8][8];
#pragma unroll
    for (int i = 0; i < 8; i++)
#pragma unroll
        for (int j = 0; j < 8; j++) acc[i][j] = 0.f;

    // bias fragment (cols tx*4..+4 and 64+tx*4..+4)
    float bfr[8];
#pragma unroll
    for (int j = 0; j < 4; j++) {
        bfr[j]     = bias[bx * 128 + tx * 4 + j];
        bfr[j + 4] = bias[bx * 128 + 64 + tx * 4 + j];
    }

    const int aRow = tid >> 2;          // 0..63 (+64 second slot)
    const int aCol = (tid & 3) * 4;     // 0..12
    const int bRow = tid >> 5;          // 0..7  (+8 second slot)
    const int bCol = (tid & 31) * 4;    // 0..124

    for (int k0 = 0; k0 < K; k0 += 16) {
        float4 a0 = *(const float4*)(Ablk + (size_t)aRow * K + k0 + aCol);
        float4 a1 = *(const float4*)(Ablk + (size_t)(aRow + 64) * K + k0 + aCol);
        float4 b0 = *(const float4*)(Bblk + (size_t)(k0 + bRow) * N + bCol);
        float4 b1 = *(const float4*)(Bblk + (size_t)(k0 + bRow + 8) * N + bCol);
        __syncthreads();
        As[aCol + 0][aRow] = a0.x; As[aCol + 1][aRow] = a0.y;
        As[aCol + 2][aRow] = a0.z; As[aCol + 3][aRow] = a0.w;
        As[aCol + 0][aRow + 64] = a1.x; As[aCol + 1][aRow + 64] = a1.y;
        As[aCol + 2][aRow + 64] = a1.z; As[aCol + 3][aRow + 64] = a1.w;
        *(float4*)&Bs[bRow][bCol] = b0;
        *(float4*)&Bs[bRow + 8][bCol] = b1;
        __syncthreads();
#pragma unroll
        for (int k = 0; k < 16; k++) {
            float4 fa0 = *(const float4*)&As[k][ty * 4];
            float4 fa1 = *(const float4*)&As[k][64 + ty * 4];
            float4 fb0 = *(const float4*)&Bs[k][tx * 4];
            float4 fb1 = *(const float4*)&Bs[k][64 + tx * 4];
            float ra[8] = {fa0.x, fa0.y, fa0.z, fa0.w, fa1.x, fa1.y, fa1.z, fa1.w};
            float rb[8] = {fb0.x, fb0.y, fb0.z, fb0.w, fb1.x, fb1.y, fb1.z, fb1.w};
#pragma unroll
            for (int i = 0; i < 8; i++)
#pragma unroll
                for (int j = 0; j < 8; j++)
                    acc[i][j] += ra[i] * rb[j];
        }
    }

    float* Cblk = C + (size_t)(by * 128) * N + bx * 128;
#pragma unroll
    for (int i = 0; i < 8; i++) {
        int row = (i < 4) ? (ty * 4 + i) : (64 + ty * 4 + (i - 4));
        float4 o0, o1;
        o0.x = acc[i][0] + bfr[0]; o0.y = acc[i][1] + bfr[1];
        o0.z = acc[i][2] + bfr[2]; o0.w = acc[i][3] + bfr[3];
        o1.x = acc[i][4] + bfr[4]; o1.y = acc[i][5] + bfr[5];
        o1.z = acc[i][6] + bfr[6]; o1.w = acc[i][7] + bfr[7];
        *(float4*)(Cblk + (size_t)row * N + tx * 4) = o0;
        *(float4*)(Cblk + (size_t)row * N + 64 + tx * 4) = o1;
    }
}

// ---------------------------------------------------------------------------
// Causal flash attention, fp32. One block = one (b, h, q-tile of 64).
// 256 threads = 16x16 grid; each thread: 4x4 score fragment, 4x8 output frag.
// Q/K stored d-major (transposed) with XOR swizzle -> conflict-free LDS.128.
// ---------------------------------------------------------------------------
__global__ __launch_bounds__(256, 2)
void flash_attn_kernel(const float* __restrict__ qkv, float* __restrict__ ctx) {
    extern __shared__ float sm[];
    float* Qst = sm;                 // [128][64] d-major, swizzled
    float* Kst = Qst + 128 * 64;     // [128][64] d-major, swizzled
    float* Vs  = Kst + 128 * 64;     // [64][128] row-major
    float* Pst = Vs + 64 * 128;      // [64][64]  c-major, swizzled

    const int tid = threadIdx.x;
    const int tx = tid & 15, ty = tid >> 4;
    const int qt = blockIdx.x;       // q tile (0..31)
    const int h  = blockIdx.y;
    const int b  = blockIdx.z;
    const float scale = 0.08838834764831845f;  // 1/sqrt(128)

    const float* base = qkv + ((size_t)b * SEQ) * K3 + h * (3 * HDIM);

    const int c4 = (tid & 31) * 4;   // d group (0..124), fixed per thread
    const int r0 = tid >> 5;         // row base, rows r0 + 8*it
    const int swm = c4 & 28;         // xor mask for this d group

    // Load Q tile transposed + pre-scaled
#pragma unroll
    for (int it = 0; it < 8; ++it) {
        int row = r0 + it * 8;
        float4 q4 = *(const float4*)(base + (size_t)(qt * 64 + row) * K3 + c4);
        int sw = row ^ swm;
        Qst[(c4 + 0) * 64 + sw] = q4.x * scale;
        Qst[(c4 + 1) * 64 + sw] = q4.y * scale;
        Qst[(c4 + 2) * 64 + sw] = q4.z * scale;
        Qst[(c4 + 3) * 64 + sw] = q4.w * scale;
    }

    float m[4], l[4], o[4][8];
#pragma unroll
    for (int i = 0; i < 4; i++) {
        m[i] = -1e30f; l[i] = 0.f;
#pragma unroll
        for (int j = 0; j < 8; j++) o[i][j] = 0.f;
    }

    const int ntiles = qt + 1;  // causal: only tiles <= diagonal
    for (int kt = 0; kt < ntiles; ++kt) {
        __syncthreads();  // prev PV reads done (and Q load on first iter)
        // Load K (transposed+swizzled) and V (row-major)
#pragma unroll
        for (int it = 0; it < 8; ++it) {
            int row = r0 + it * 8;
            const float* rp = base + (size_t)(kt * 64 + row) * K3;
            float4 k4 = *(const float4*)(rp + HDIM + c4);
            int sw = row ^ swm;
            Kst[(c4 + 0) * 64 + sw] = k4.x;
            Kst[(c4 + 1) * 64 + sw] = k4.y;
            Kst[(c4 + 2) * 64 + sw] = k4.z;
            Kst[(c4 + 3) * 64 + sw] = k4.w;
            float4 v4 = *(const float4*)(rp + 2 * HDIM + c4);
            *(float4*)&Vs[row * 128 + c4] = v4;
        }
        __syncthreads();

        // S = Q @ K^T (already scaled via Q)
        float s[4][4];
#pragma unroll
        for (int i = 0; i < 4; i++)
#pragma unroll
            for (int j = 0; j < 4; j++) s[i][j] = 0.f;
#pragma unroll 16
        for (int d = 0; d < 128; ++d) {
            float4 q4 = *(const float4*)&Qst[d * 64 + ((ty * 4) ^ (d & 28))];
            float4 k4 = *(const float4*)&Kst[d * 64 + ((tx * 4) ^ (d & 28))];
            float rq[4] = {q4.x, q4.y, q4.z, q4.w};
            float rk[4] = {k4.x, k4.y, k4.z, k4.w};
#pragma unroll
            for (int i = 0; i < 4; i++)
#pragma unroll
                for (int j = 0; j < 4; j++)
                    s[i][j] += rq[i] * rk[j];
        }

        // Causal mask only needed on the diagonal tile
        if (kt == qt) {
#pragma unroll
            for (int i = 0; i < 4; i++)
#pragma unroll
                for (int j = 0; j < 4; j++)
                    if (tx * 4 + j > ty * 4 + i) s[i][j] = -1e30f;
        }

        // Online softmax per row + write P transposed (swizzled)
        const int pswm = (tx * 4) & 28;
#pragma unroll
        for (int i = 0; i < 4; i++) {
            float mx = fmaxf(fmaxf(s[i][0], s[i][1]), fmaxf(s[i][2], s[i][3]));
#pragma unroll
            for (int off = 8; off >= 1; off >>= 1)
                mx = fmaxf(mx, __shfl_xor_sync(0xffffffffu, mx, off));
            float mn = fmaxf(m[i], mx);
            float alpha = __expf(m[i] - mn);
            float p0 = __expf(s[i][0] - mn);
            float p1 = __expf(s[i][1] - mn);
            float p2 = __expf(s[i][2] - mn);
            float p3 = __expf(s[i][3] - mn);
            float ls = p0 + p1 + p2 + p3;
#pragma unroll
            for (int off = 8; off >= 1; off >>= 1)
                ls += __shfl_xor_sync(0xffffffffu, ls, off);
            l[i] = l[i] * alpha + ls;
            m[i] = mn;
#pragma unroll
            for (int j = 0; j < 8; j++) o[i][j] *= alpha;
            int r = ty * 4 + i;
            int rsw = r ^ pswm;
            Pst[(tx * 4 + 0) * 64 + rsw] = p0;
            Pst[(tx * 4 + 1) * 64 + rsw] = p1;
            Pst[(tx * 4 + 2) * 64 + rsw] = p2;
            Pst[(tx * 4 + 3) * 64 + rsw] = p3;
        }
        __syncthreads();

        // O += P @ V
#pragma unroll 8
        for (int c = 0; c < 64; ++c) {
            float4 p4 = *(const float4*)&Pst[c * 64 + ((ty * 4) ^ (c & 28))];
            float4 v0 = *(const float4*)&Vs[c * 128 + tx * 4];
            float4 v1 = *(const float4*)&Vs[c * 128 + 64 + tx * 4];
            float rp[4] = {p4.x, p4.y, p4.z, p4.w};
            float rv[8] = {v0.x, v0.y, v0.z, v0.w, v1.x, v1.y, v1.z, v1.w};
#pragma unroll
            for (int i = 0; i < 4; i++)
#pragma unroll
                for (int j = 0; j < 8; j++)
                    o[i][j] += rp[i] * rv[j];
        }
    }

    // Epilogue: normalize and write ctx[b, s, h*128 + d]
    const size_t obase = ((size_t)b * SEQ + (size_t)qt * 64) * HID + (size_t)h * HDIM;
#pragma unroll
    for (int i = 0; i < 4; i++) {
        float inv = 1.f / l[i];
        int row = ty * 4 + i;
        float4 w0, w1;
        w0.x = o[i][0] * inv; w0.y = o[i][1] * inv;
        w0.z = o[i][2] * inv; w0.w = o[i][3] * inv;
        w1.x = o[i][4] * inv; w1.y = o[i][5] * inv;
        w1.z = o[i][6] * inv; w1.w = o[i][7] * inv;
        *(float4*)(ctx + obase + (size_t)row * HID + tx * 4) = w0;
        *(float4*)(ctx + obase + (size_t)row * HID + 64 + tx * 4) = w1;
    }
}

// ---------------------------------------------------------------------------
extern "C" void kernel_launch(void* const* d_in, const int* in_sizes, int n_in,
                              void* d_out, int out_size) {
    const float* x      = (const float*)d_in[0];  // [B,S,H]
    const float* w_qkv  = (const float*)d_in[1];  // [H, 3H]
    const float* b_qkv  = (const float*)d_in[2];  // [3H]
    const float* w_out  = (const float*)d_in[3];  // [H, H]
    const float* b_out  = (const float*)d_in[4];  // [H]
    float* out = (float*)d_out;                   // [B,S,H]

    float* qkv; cudaGetSymbolAddress((void**)&qkv, g_qkv);
    float* ctx; cudaGetSymbolAddress((void**)&ctx, g_ctx);

    const int smem_attn = (128 * 64 + 128 * 64 + 64 * 128 + 64 * 64) * 4; // 114688
    cudaFuncSetAttribute(flash_attn_kernel,
                         cudaFuncAttributeMaxDynamicSharedMemorySize, smem_attn);

    // 1) QKV projection: [4096,2048] @ [2048,6144] + bias
    sgemm_bias_kernel<<<dim3(K3 / 128, MROWS / 128), 256>>>(x, w_qkv, b_qkv, qkv, K3, HID);

    // 2) Causal flash attention per (q-tile, head, batch)
    flash_attn_kernel<<<dim3(SEQ / 64, NHEAD, BATCH), 256, smem_attn>>>(qkv, ctx);

    // 3) Output projection: [4096,2048] @ [2048,2048] + bias
    sgemm_bias_kernel<<<dim3(HID / 128, MROWS / 128), 256>>>(ctx, w_out, b_out, out, HID, HID);
}

// round 2
// speedup vs baseline: 1.8798x; 1.8798x over previous
#include <cuda_runtime.h>

// Problem constants
#define BATCH 2
#define SEQ   2048
#define HID   2048
#define NHEAD 16
#define HDIM  128
#define MROWS (BATCH * SEQ)   // 4096
#define K3    (3 * HID)       // 6144

// Scratch (allocation-free rule: __device__ globals)
__device__ float g_qkv[(size_t)MROWS * K3];  // [4096, 6144]
__device__ float g_ctx[(size_t)MROWS * HID]; // [4096, 2048]

// ---------------------------------------------------------------------------
// tf32 tensor-core SGEMM: C[M,N] = A[M,K] @ B[K,N] + bias[N]
// Block 128x128, BK=32, 256 threads (8 warps: 2m x 4n, warp tile 64x32).
// mma.sync.m16n8k8 tf32. A smem XOR-swizzled (k ^ (m&3)*8) so fragment reads
// are conflict-free LDS.64; B smem row stride 132 (pad) -> conflict-free LDS.32.
// k-permutation: mma col c maps to k = 2c (c<4) / 2(c-4)+1 (c>=4) so each
// thread's two k-values per fragment are adjacent (float2 loads from A).
// cp.async double-buffered global->smem pipeline.
// ---------------------------------------------------------------------------

__device__ __forceinline__ unsigned f2tf(float x) {
    unsigned u;
    asm("cvt.rna.tf32.f32 %0, %1;" : "=r"(u) : "f"(x));
    return u;
}

__device__ __forceinline__ void mma_tf32(float* d, const unsigned* a, const unsigned* b) {
    asm volatile(
        "mma.sync.aligned.m16n8k8.row.col.f32.tf32.tf32.f32 "
        "{%0,%1,%2,%3},{%4,%5,%6,%7},{%8,%9},{%0,%1,%2,%3};"
        : "+f"(d[0]), "+f"(d[1]), "+f"(d[2]), "+f"(d[3])
        : "r"(a[0]), "r"(a[1]), "r"(a[2]), "r"(a[3]), "r"(b[0]), "r"(b[1]));
}

__device__ __forceinline__ void cp16(unsigned dst, const void* src) {
    asm volatile("cp.async.cg.shared.global [%0], [%1], 16;\n" :: "r"(dst), "l"(src));
}

// smem layout (words): A stage s at s*4096 ; B stage s at 8192 + s*4224
#define A_STAGE_W 4096
#define B_BASE_W  8192
#define B_STAGE_W 4224
#define BSTR      132
#define SMEM_GEMM_BYTES ((B_BASE_W + 2 * B_STAGE_W) * 4)   // 66560

__global__ __launch_bounds__(256)
void sgemm_tf32_kernel(const float* __restrict__ A, const float* __restrict__ Bw,
                       const float* __restrict__ bias, float* __restrict__ C,
                       int N, int K) {
    extern __shared__ float sm[];
    const int tid = threadIdx.x;
    const int lane = tid & 31;
    const int warp = tid >> 5;
    const int wm = warp & 1;        // 0..1
    const int wn = warp >> 1;       // 0..3
    const int bm = blockIdx.y * 128;
    const int bn = blockIdx.x * 128;

    const int g = lane >> 2;        // group 0..7
    const int c = lane & 3;         // 0..3
    const int swz = (g & 3) * 8;    // A fragment swizzle mask (m&3 == g&3)

    // copy thread mapping
    const int am = tid >> 3;              // 0..31 (A row)
    const int aj = (tid & 7) * 4;         // A k-word
    const int bk = tid >> 3;              // 0..31 (B k-row)
    const int bnn = (tid & 7) * 4;        // B n-word

    unsigned smu;
    { unsigned long long p = __cvta_generic_to_shared(sm); smu = (unsigned)p; }
    const unsigned aDst = smu + (unsigned)(am * 32 + (aj ^ ((am & 3) * 8))) * 4;
    const unsigned bDst = smu + (unsigned)(B_BASE_W + bk * BSTR + bnn) * 4;

    const float* aSrcBase = A + (size_t)(bm + am) * K + aj;
    const float* bSrcBase = Bw + (size_t)bk * N + bn + bnn;

    float acc[4][4][4];
#pragma unroll
    for (int mt = 0; mt < 4; mt++)
#pragma unroll
        for (int nt = 0; nt < 4; nt++)
#pragma unroll
            for (int r = 0; r < 4; r++) acc[mt][nt][r] = 0.f;

    const int T = K / 32;

    // prologue: stage 0
    {
        const float* as = aSrcBase;
        const float* bs = bSrcBase;
#pragma unroll
        for (int r = 0; r < 4; r++) {
            cp16(aDst + (unsigned)(r * 32 * 32) * 4, as + (size_t)(r * 32) * K);
            cp16(bDst + (unsigned)(r * 32) * 4, bs + r * 32);
        }
        asm volatile("cp.async.commit_group;\n");
    }

    for (int i = 0; i < T; i++) {
        if (i + 1 < T) {
            const int ns = (i + 1) & 1;
            const float* as = aSrcBase + (i + 1) * 32;
            const float* bs = bSrcBase + (size_t)((i + 1) * 32) * N;
            const unsigned ad = aDst + (unsigned)(ns * A_STAGE_W) * 4;
            const unsigned bd = bDst + (unsigned)(ns * B_STAGE_W) * 4;
#pragma unroll
            for (int r = 0; r < 4; r++) {
                cp16(ad + (unsigned)(r * 32 * 32) * 4, as + (size_t)(r * 32) * K);
                cp16(bd + (unsigned)(r * 32) * 4, bs + r * 32);
            }
        }
        asm volatile("cp.async.commit_group;\n");
        asm volatile("cp.async.wait_group 1;\n");
        __syncthreads();

        const int st = i & 1;
        const float* As = sm + st * A_STAGE_W;
        const float* Bs = sm + B_BASE_W + st * B_STAGE_W;

#pragma unroll
        for (int s = 0; s < 4; s++) {
            const int kof = (8 * s + 2 * c) ^ swz;   // swizzled k word (float2-aligned)
            unsigned av[4][4];
#pragma unroll
            for (int mt = 0; mt < 4; mt++) {
                const float* pa = As + (wm * 64 + mt * 16 + g) * 32 + kof;
                float2 f0 = *(const float2*)pa;
                float2 f1 = *(const float2*)(pa + 8 * 32);
                av[mt][0] = f2tf(f0.x);
                av[mt][2] = f2tf(f0.y);
                av[mt][1] = f2tf(f1.x);
                av[mt][3] = f2tf(f1.y);
            }
            unsigned bv[4][2];
            const float* pbBase = Bs + (8 * s + 2 * c) * BSTR + wn * 32 + g;
#pragma unroll
            for (int nt = 0; nt < 4; nt++) {
                const float* pb = pbBase + nt * 8;
                bv[nt][0] = f2tf(pb[0]);
                bv[nt][1] = f2tf(pb[BSTR]);
            }
#pragma unroll
            for (int mt = 0; mt < 4; mt++)
#pragma unroll
                for (int nt = 0; nt < 4; nt++)
                    mma_tf32(acc[mt][nt], av[mt], bv[nt]);
        }
        __syncthreads();
    }

    // epilogue: add bias, write float2 pairs
#pragma unroll
    for (int mt = 0; mt < 4; mt++) {
        const int row = bm + wm * 64 + mt * 16 + g;
#pragma unroll
        for (int nt = 0; nt < 4; nt++) {
            const int col = bn + wn * 32 + nt * 8 + 2 * c;
            const float b0 = __ldg(&bias[col]);
            const float b1 = __ldg(&bias[col + 1]);
            float2 o0, o1;
            o0.x = acc[mt][nt][0] + b0; o0.y = acc[mt][nt][1] + b1;
            o1.x = acc[mt][nt][2] + b0; o1.y = acc[mt][nt][3] + b1;
            *(float2*)(C + (size_t)row * N + col) = o0;
            *(float2*)(C + (size_t)(row + 8) * N + col) = o1;
        }
    }
}

// ---------------------------------------------------------------------------
// Causal flash attention, fp32 (unchanged from round 1).
// ---------------------------------------------------------------------------
__global__ __launch_bounds__(256, 2)
void flash_attn_kernel(const float* __restrict__ qkv, float* __restrict__ ctx) {
    extern __shared__ float sm[];
    float* Qst = sm;                 // [128][64] d-major, swizzled
    float* Kst = Qst + 128 * 64;     // [128][64] d-major, swizzled
    float* Vs  = Kst + 128 * 64;     // [64][128] row-major
    float* Pst = Vs + 64 * 128;      // [64][64]  c-major, swizzled

    const int tid = threadIdx.x;
    const int tx = tid & 15, ty = tid >> 4;
    const int qt = blockIdx.x;
    const int h  = blockIdx.y;
    const int b  = blockIdx.z;
    const float scale = 0.08838834764831845f;

    const float* base = qkv + ((size_t)b * SEQ) * K3 + h * (3 * HDIM);

    const int c4 = (tid & 31) * 4;
    const int r0 = tid >> 5;
    const int swm = c4 & 28;

#pragma unroll
    for (int it = 0; it < 8; ++it) {
        int row = r0 + it * 8;
        float4 q4 = *(const float4*)(base + (size_t)(qt * 64 + row) * K3 + c4);
        int sw = row ^ swm;
        Qst[(c4 + 0) * 64 + sw] = q4.x * scale;
        Qst[(c4 + 1) * 64 + sw] = q4.y * scale;
        Qst[(c4 + 2) * 64 + sw] = q4.z * scale;
        Qst[(c4 + 3) * 64 + sw] = q4.w * scale;
    }

    float m[4], l[4], o[4][8];
#pragma unroll
    for (int i = 0; i < 4; i++) {
        m[i] = -1e30f; l[i] = 0.f;
#pragma unroll
        for (int j = 0; j < 8; j++) o[i][j] = 0.f;
    }

    const int ntiles = qt + 1;
    for (int kt = 0; kt < ntiles; ++kt) {
        __syncthreads();
#pragma unroll
        for (int it = 0; it < 8; ++it) {
            int row = r0 + it * 8;
            const float* rp = base + (size_t)(kt * 64 + row) * K3;
            float4 k4 = *(const float4*)(rp + HDIM + c4);
            int sw = row ^ swm;
            Kst[(c4 + 0) * 64 + sw] = k4.x;
            Kst[(c4 + 1) * 64 + sw] = k4.y;
            Kst[(c4 + 2) * 64 + sw] = k4.z;
            Kst[(c4 + 3) * 64 + sw] = k4.w;
            float4 v4 = *(const float4*)(rp + 2 * HDIM + c4);
            *(float4*)&Vs[row * 128 + c4] = v4;
        }
        __syncthreads();

        float s[4][4];
#pragma unroll
        for (int i = 0; i < 4; i++)
#pragma unroll
            for (int j = 0; j < 4; j++) s[i][j] = 0.f;
#pragma unroll 16
        for (int d = 0; d < 128; ++d) {
            float4 q4 = *(const float4*)&Qst[d * 64 + ((ty * 4) ^ (d & 28))];
            float4 k4 = *(const float4*)&Kst[d * 64 + ((tx * 4) ^ (d & 28))];
            float rq[4] = {q4.x, q4.y, q4.z, q4.w};
            float rk[4] = {k4.x, k4.y, k4.z, k4.w};
#pragma unroll
            for (int i = 0; i < 4; i++)
#pragma unroll
                for (int j = 0; j < 4; j++)
                    s[i][j] += rq[i] * rk[j];
        }

        if (kt == qt) {
#pragma unroll
            for (int i = 0; i < 4; i++)
#pragma unroll
                for (int j = 0; j < 4; j++)
                    if (tx * 4 + j > ty * 4 + i) s[i][j] = -1e30f;
        }

        const int pswm = (tx * 4) & 28;
#pragma unroll
        for (int i = 0; i < 4; i++) {
            float mx = fmaxf(fmaxf(s[i][0], s[i][1]), fmaxf(s[i][2], s[i][3]));
#pragma unroll
            for (int off = 8; off >= 1; off >>= 1)
                mx = fmaxf(mx, __shfl_xor_sync(0xffffffffu, mx, off));
            float mn = fmaxf(m[i], mx);
            float alpha = __expf(m[i] - mn);
            float p0 = __expf(s[i][0] - mn);
            float p1 = __expf(s[i][1] - mn);
            float p2 = __expf(s[i][2] - mn);
            float p3 = __expf(s[i][3] - mn);
            float ls = p0 + p1 + p2 + p3;
#pragma unroll
            for (int off = 8; off >= 1; off >>= 1)
                ls += __shfl_xor_sync(0xffffffffu, ls, off);
            l[i] = l[i] * alpha + ls;
            m[i] = mn;
#pragma unroll
            for (int j = 0; j < 8; j++) o[i][j] *= alpha;
            int r = ty * 4 + i;
            int rsw = r ^ pswm;
            Pst[(tx * 4 + 0) * 64 + rsw] = p0;
            Pst[(tx * 4 + 1) * 64 + rsw] = p1;
            Pst[(tx * 4 + 2) * 64 + rsw] = p2;
            Pst[(tx * 4 + 3) * 64 + rsw] = p3;
        }
        __syncthreads();

#pragma unroll 8
        for (int cc = 0; cc < 64; ++cc) {
            float4 p4 = *(const float4*)&Pst[cc * 64 + ((ty * 4) ^ (cc & 28))];
            float4 v0 = *(const float4*)&Vs[cc * 128 + tx * 4];
            float4 v1 = *(const float4*)&Vs[cc * 128 + 64 + tx * 4];
            float rp[4] = {p4.x, p4.y, p4.z, p4.w};
            float rv[8] = {v0.x, v0.y, v0.z, v0.w, v1.x, v1.y, v1.z, v1.w};
#pragma unroll
            for (int i = 0; i < 4; i++)
#pragma unroll
                for (int j = 0; j < 8; j++)
                    o[i][j] += rp[i] * rv[j];
        }
    }

    const size_t obase = ((size_t)b * SEQ + (size_t)qt * 64) * HID + (size_t)h * HDIM;
#pragma unroll
    for (int i = 0; i < 4; i++) {
        float inv = 1.f / l[i];
        int row = ty * 4 + i;
        float4 w0, w1;
        w0.x = o[i][0] * inv; w0.y = o[i][1] * inv;
        w0.z = o[i][2] * inv; w0.w = o[i][3] * inv;
        w1.x = o[i][4] * inv; w1.y = o[i][5] * inv;
        w1.z = o[i][6] * inv; w1.w = o[i][7] * inv;
        *(float4*)(ctx + obase + (size_t)row * HID + tx * 4) = w0;
        *(float4*)(ctx + obase + (size_t)row * HID + 64 + tx * 4) = w1;
    }
}

// ---------------------------------------------------------------------------
extern "C" void kernel_launch(void* const* d_in, const int* in_sizes, int n_in,
                              void* d_out, int out_size) {
    const float* x      = (const float*)d_in[0];
    const float* w_qkv  = (const float*)d_in[1];
    const float* b_qkv  = (const float*)d_in[2];
    const float* w_out  = (const float*)d_in[3];
    const float* b_out  = (const float*)d_in[4];
    float* out = (float*)d_out;

    float* qkv; cudaGetSymbolAddress((void**)&qkv, g_qkv);
    float* ctx; cudaGetSymbolAddress((void**)&ctx, g_ctx);

    const int smem_attn = (128 * 64 + 128 * 64 + 64 * 128 + 64 * 64) * 4; // 114688
    cudaFuncSetAttribute(flash_attn_kernel,
                         cudaFuncAttributeMaxDynamicSharedMemorySize, smem_attn);
    cudaFuncSetAttribute(sgemm_tf32_kernel,
                         cudaFuncAttributeMaxDynamicSharedMemorySize, SMEM_GEMM_BYTES);

    // 1) QKV projection: [4096,2048] @ [2048,6144] + bias
    sgemm_tf32_kernel<<<dim3(K3 / 128, MROWS / 128), 256, SMEM_GEMM_BYTES>>>(
        x, w_qkv, b_qkv, qkv, K3, HID);

    // 2) Causal flash attention per (q-tile, head, batch)
    flash_attn_kernel<<<dim3(SEQ / 64, NHEAD, BATCH), 256, smem_attn>>>(qkv, ctx);

    // 3) Output projection: [4096,2048] @ [2048,2048] + bias
    sgemm_tf32_kernel<<<dim3(HID / 128, MROWS / 128), 256, SMEM_GEMM_BYTES>>>(
        ctx, w_out, b_out, out, HID, HID);
}

// round 3
// speedup vs baseline: 3.3720x; 1.7938x over previous
#include <cuda_runtime.h>

// Problem constants
#define BATCH 2
#define SEQ   2048
#define HID   2048
#define NHEAD 16
#define HDIM  128
#define MROWS (BATCH * SEQ)   // 4096
#define K3    (3 * HID)       // 6144

// Scratch (allocation-free rule: __device__ globals)
__device__ float g_qkv[(size_t)MROWS * K3];  // [4096, 6144]
__device__ float g_ctx[(size_t)MROWS * HID]; // [4096, 2048]

__device__ __forceinline__ unsigned f2tf(float x) {
    unsigned u;
    asm("cvt.rna.tf32.f32 %0, %1;" : "=r"(u) : "f"(x));
    return u;
}

__device__ __forceinline__ void mma_tf32(float* d, const unsigned* a, const unsigned* b) {
    asm volatile(
        "mma.sync.aligned.m16n8k8.row.col.f32.tf32.tf32.f32 "
        "{%0,%1,%2,%3},{%4,%5,%6,%7},{%8,%9},{%0,%1,%2,%3};"
        : "+f"(d[0]), "+f"(d[1]), "+f"(d[2]), "+f"(d[3])
        : "r"(a[0]), "r"(a[1]), "r"(a[2]), "r"(a[3]), "r"(b[0]), "r"(b[1]));
}

__device__ __forceinline__ void cp16(unsigned dst, const void* src) {
    asm volatile("cp.async.cg.shared.global [%0], [%1], 16;\n" :: "r"(dst), "l"(src));
}

// ===========================================================================
// tf32 tensor-core SGEMM (unchanged from round 2)
// ===========================================================================
#define A_STAGE_W 4096
#define B_BASE_W  8192
#define B_STAGE_W 4224
#define BSTR      132
#define SMEM_GEMM_BYTES ((B_BASE_W + 2 * B_STAGE_W) * 4)   // 66560

__global__ __launch_bounds__(256)
void sgemm_tf32_kernel(const float* __restrict__ A, const float* __restrict__ Bw,
                       const float* __restrict__ bias, float* __restrict__ C,
                       int N, int K) {
    extern __shared__ float sm[];
    const int tid = threadIdx.x;
    const int lane = tid & 31;
    const int warp = tid >> 5;
    const int wm = warp & 1;
    const int wn = warp >> 1;
    const int bm = blockIdx.y * 128;
    const int bn = blockIdx.x * 128;

    const int g = lane >> 2;
    const int c = lane & 3;
    const int swz = (g & 3) * 8;

    const int am = tid >> 3;
    const int aj = (tid & 7) * 4;
    const int bk = tid >> 3;
    const int bnn = (tid & 7) * 4;

    unsigned smu;
    { unsigned long long p = __cvta_generic_to_shared(sm); smu = (unsigned)p; }
    const unsigned aDst = smu + (unsigned)(am * 32 + (aj ^ ((am & 3) * 8))) * 4;
    const unsigned bDst = smu + (unsigned)(B_BASE_W + bk * BSTR + bnn) * 4;

    const float* aSrcBase = A + (size_t)(bm + am) * K + aj;
    const float* bSrcBase = Bw + (size_t)bk * N + bn + bnn;

    float acc[4][4][4];
#pragma unroll
    for (int mt = 0; mt < 4; mt++)
#pragma unroll
        for (int nt = 0; nt < 4; nt++)
#pragma unroll
            for (int r = 0; r < 4; r++) acc[mt][nt][r] = 0.f;

    const int T = K / 32;

    {
        const float* as = aSrcBase;
        const float* bs = bSrcBase;
#pragma unroll
        for (int r = 0; r < 4; r++) {
            cp16(aDst + (unsigned)(r * 32 * 32) * 4, as + (size_t)(r * 32) * K);
            cp16(bDst + (unsigned)(r * 32) * 4, bs + r * 32);
        }
        asm volatile("cp.async.commit_group;\n");
    }

    for (int i = 0; i < T; i++) {
        if (i + 1 < T) {
            const int ns = (i + 1) & 1;
            const float* as = aSrcBase + (i + 1) * 32;
            const float* bs = bSrcBase + (size_t)((i + 1) * 32) * N;
            const unsigned ad = aDst + (unsigned)(ns * A_STAGE_W) * 4;
            const unsigned bd = bDst + (unsigned)(ns * B_STAGE_W) * 4;
#pragma unroll
            for (int r = 0; r < 4; r++) {
                cp16(ad + (unsigned)(r * 32 * 32) * 4, as + (size_t)(r * 32) * K);
                cp16(bd + (unsigned)(r * 32) * 4, bs + r * 32);
            }
        }
        asm volatile("cp.async.commit_group;\n");
        asm volatile("cp.async.wait_group 1;\n");
        __syncthreads();

        const int st = i & 1;
        const float* As = sm + st * A_STAGE_W;
        const float* Bs = sm + B_BASE_W + st * B_STAGE_W;

#pragma unroll
        for (int s = 0; s < 4; s++) {
            const int kof = (8 * s + 2 * c) ^ swz;
            unsigned av[4][4];
#pragma unroll
            for (int mt = 0; mt < 4; mt++) {
                const float* pa = As + (wm * 64 + mt * 16 + g) * 32 + kof;
                float2 f0 = *(const float2*)pa;
                float2 f1 = *(const float2*)(pa + 8 * 32);
                av[mt][0] = f2tf(f0.x);
                av[mt][2] = f2tf(f0.y);
                av[mt][1] = f2tf(f1.x);
                av[mt][3] = f2tf(f1.y);
            }
            unsigned bv[4][2];
            const float* pbBase = Bs + (8 * s + 2 * c) * BSTR + wn * 32 + g;
#pragma unroll
            for (int nt = 0; nt < 4; nt++) {
                const float* pb = pbBase + nt * 8;
                bv[nt][0] = f2tf(pb[0]);
                bv[nt][1] = f2tf(pb[BSTR]);
            }
#pragma unroll
            for (int mt = 0; mt < 4; mt++)
#pragma unroll
                for (int nt = 0; nt < 4; nt++)
                    mma_tf32(acc[mt][nt], av[mt], bv[nt]);
        }
        __syncthreads();
    }

#pragma unroll
    for (int mt = 0; mt < 4; mt++) {
        const int row = bm + wm * 64 + mt * 16 + g;
#pragma unroll
        for (int nt = 0; nt < 4; nt++) {
            const int col = bn + wn * 32 + nt * 8 + 2 * c;
            const float b0 = __ldg(&bias[col]);
            const float b1 = __ldg(&bias[col + 1]);
            float2 o0, o1;
            o0.x = acc[mt][nt][0] + b0; o0.y = acc[mt][nt][1] + b1;
            o1.x = acc[mt][nt][2] + b0; o1.y = acc[mt][nt][3] + b1;
            *(float2*)(C + (size_t)row * N + col) = o0;
            *(float2*)(C + (size_t)(row + 8) * N + col) = o1;
        }
    }
}

// ===========================================================================
// In-place rna-tf32 truncation of g_qkv (so attention needs no CVT at all)
// ===========================================================================
__global__ void tf32_round_kernel(float4* __restrict__ p, int n4) {
    int i = blockIdx.x * blockDim.x + threadIdx.x;
    if (i < n4) {
        float4 v = p[i];
        v.x = __uint_as_float(f2tf(v.x));
        v.y = __uint_as_float(f2tf(v.y));
        v.z = __uint_as_float(f2tf(v.z));
        v.w = __uint_as_float(f2tf(v.w));
        p[i] = v;
    }
}

// ===========================================================================
// Tensor-core causal flash attention (tf32 mma).
// BQ=128, BKV=64. 256 threads = 8 warps, each owns 16 q-rows (full row in warp).
// S-accumulator fragments are reused directly as P A-operands (k-permutation
// makes layouts match) -> P never goes to smem.
// smem: K stage [64][128] swizzled, V stage [64][132] padded; double-buffered.
// ===========================================================================
#define K_STW 8192              // 64*128 words per K stage
#define V_STW 8448              // 64*132 words per V stage
#define V_BASE_W 16384          // after 2 K stages
#define AT_SMEM_BYTES ((V_BASE_W + 2 * V_STW) * 4)   // 133120

__global__ __launch_bounds__(256, 1)
void flash_attn_tc_kernel(const float* __restrict__ qkv, float* __restrict__ ctx) {
    extern __shared__ float sm[];
    const int tid = threadIdx.x;
    const int lane = tid & 31;
    const int wid = tid >> 5;
    const int g = lane >> 2;
    const int c = lane & 3;
    const int qt = 15 - blockIdx.x;       // heavy tiles first
    const int h = blockIdx.y;
    const int b = blockIdx.z;
    const int q0 = qt * 128;
    const float scale = 0.08838834764831845f;  // 1/sqrt(128)

    const float* base = qkv + ((size_t)b * SEQ) * K3 + (size_t)h * (3 * HDIM);

    unsigned smu;
    { unsigned long long p = __cvta_generic_to_shared(sm); smu = (unsigned)p; }

    // ---- copy mapping: 8 chunks (16B) per thread per tensor per tile ----
    // chunk = tid + 256*r : row = chunk>>5 (0..63), word = (chunk&31)*4
    // ---- issue tile 0 K/V copies ----
    const int ntiles = 2 * qt + 2;

    auto issue_tile = [&](int j, int st) {
        const float* kvb = base + (size_t)(j * 64) * K3;
#pragma unroll
        for (int r = 0; r < 8; r++) {
            int chunk = tid + 256 * r;
            int row = chunk >> 5;
            int cw = (chunk & 31) * 4;
            const float* src = kvb + (size_t)row * K3 + cw;
            unsigned kd = smu + (unsigned)(st * K_STW + row * 128 + (cw ^ ((row & 3) * 8))) * 4;
            unsigned vd = smu + (unsigned)(V_BASE_W + st * V_STW + row * 132 + cw) * 4;
            cp16(kd, src + HDIM);
            cp16(vd, src + 2 * HDIM);
        }
    };

    issue_tile(0, 0);
    asm volatile("cp.async.commit_group;\n");

    // ---- load Q fragments (bits already tf32 from pre-pass) ----
    unsigned qf[16][4];
    {
        const float* qrow = base + (size_t)(q0 + wid * 16 + g) * K3;
        const float* qrow8 = qrow + 8 * (size_t)K3;
#pragma unroll
        for (int s = 0; s < 16; s++) {
            float2 f0 = *(const float2*)(qrow + 8 * s + 2 * c);
            float2 f1 = *(const float2*)(qrow8 + 8 * s + 2 * c);
            qf[s][0] = __float_as_uint(f0.x);
            qf[s][2] = __float_as_uint(f0.y);
            qf[s][1] = __float_as_uint(f1.x);
            qf[s][3] = __float_as_uint(f1.y);
        }
    }

    float o[16][4];
#pragma unroll
    for (int nt = 0; nt < 16; nt++)
#pragma unroll
        for (int r = 0; r < 4; r++) o[nt][r] = 0.f;
    float m0 = -1e30f, m1 = -1e30f, l0 = 0.f, l1 = 0.f;

    const int rowg0 = q0 + wid * 16 + g;   // this thread's row (d0/d1)
    const int rowg1 = rowg0 + 8;           // row for d2/d3

    for (int j = 0; j < ntiles; j++) {
        if (j + 1 < ntiles) issue_tile(j + 1, (j + 1) & 1);
        asm volatile("cp.async.commit_group;\n");
        asm volatile("cp.async.wait_group 1;\n");
        __syncthreads();

        const int st = j & 1;
        const float* Ks = sm + st * K_STW;
        const float* Vs = sm + V_BASE_W + st * V_STW;

        // ---- S = Q @ K^T ----
        float sv[8][4];
#pragma unroll
        for (int nt = 0; nt < 8; nt++)
#pragma unroll
            for (int r = 0; r < 4; r++) sv[nt][r] = 0.f;

#pragma unroll
        for (int s = 0; s < 16; s++) {
            const int kof = (8 * s + 2 * c) ^ ((g & 3) * 8);
#pragma unroll
            for (int nt = 0; nt < 8; nt++) {
                float2 kf = *(const float2*)(Ks + (nt * 8 + g) * 128 + kof);
                unsigned bv[2] = {__float_as_uint(kf.x), __float_as_uint(kf.y)};
                mma_tf32(sv[nt], qf[s], bv);
            }
        }

        // ---- scale + causal mask (tail tiles only) ----
#pragma unroll
        for (int nt = 0; nt < 8; nt++)
#pragma unroll
            for (int r = 0; r < 4; r++) sv[nt][r] *= scale;

        if (j >= 2 * qt) {
            const int kv0 = j * 64;
#pragma unroll
            for (int nt = 0; nt < 8; nt++) {
                const int col = kv0 + nt * 8 + 2 * c;
                if (col     > rowg0) sv[nt][0] = -1e30f;
                if (col + 1 > rowg0) sv[nt][1] = -1e30f;
                if (col     > rowg1) sv[nt][2] = -1e30f;
                if (col + 1 > rowg1) sv[nt][3] = -1e30f;
            }
        }

        // ---- online softmax (rows g / g+8; quad shuffle = full row) ----
        float mx0 = -1e30f, mx1 = -1e30f;
#pragma unroll
        for (int nt = 0; nt < 8; nt++) {
            mx0 = fmaxf(mx0, fmaxf(sv[nt][0], sv[nt][1]));
            mx1 = fmaxf(mx1, fmaxf(sv[nt][2], sv[nt][3]));
        }
        mx0 = fmaxf(mx0, __shfl_xor_sync(0xffffffffu, mx0, 1));
        mx0 = fmaxf(mx0, __shfl_xor_sync(0xffffffffu, mx0, 2));
        mx1 = fmaxf(mx1, __shfl_xor_sync(0xffffffffu, mx1, 1));
        mx1 = fmaxf(mx1, __shfl_xor_sync(0xffffffffu, mx1, 2));

        const float mn0 = fmaxf(m0, mx0);
        const float mn1 = fmaxf(m1, mx1);
        const float a0 = __expf(m0 - mn0);
        const float a1 = __expf(m1 - mn1);
        m0 = mn0; m1 = mn1;

        float l0a = 0.f, l1a = 0.f;
        unsigned pf[8][4];
#pragma unroll
        for (int nt = 0; nt < 8; nt++) {
            float p0 = __expf(sv[nt][0] - mn0);
            float p1 = __expf(sv[nt][1] - mn0);
            float p2 = __expf(sv[nt][2] - mn1);
            float p3 = __expf(sv[nt][3] - mn1);
            l0a += p0 + p1;
            l1a += p2 + p3;
            // A-operand order: a0=P[g][k], a1=P[g+8][k], a2=P[g][k+1], a3=P[g+8][k+1]
            pf[nt][0] = f2tf(p0);
            pf[nt][1] = f2tf(p2);
            pf[nt][2] = f2tf(p1);
            pf[nt][3] = f2tf(p3);
        }
        l0 = l0 * a0 + l0a;
        l1 = l1 * a1 + l1a;

#pragma unroll
        for (int nt = 0; nt < 16; nt++) {
            o[nt][0] *= a0; o[nt][1] *= a0;
            o[nt][2] *= a1; o[nt][3] *= a1;
        }

        // ---- O += P @ V ----
#pragma unroll
        for (int s = 0; s < 8; s++) {
            const float* vrow = Vs + (8 * s + 2 * c) * 132 + g;
#pragma unroll
            for (int nt = 0; nt < 16; nt++) {
                unsigned bv[2] = {__float_as_uint(vrow[nt * 8]),
                                  __float_as_uint(vrow[nt * 8 + 132])};
                mma_tf32(o[nt], pf[s], bv);
            }
        }
        __syncthreads();
    }

    // ---- epilogue: reduce l across quad, normalize, store ----
    l0 += __shfl_xor_sync(0xffffffffu, l0, 1);
    l0 += __shfl_xor_sync(0xffffffffu, l0, 2);
    l1 += __shfl_xor_sync(0xffffffffu, l1, 1);
    l1 += __shfl_xor_sync(0xffffffffu, l1, 2);
    const float inv0 = 1.f / l0;
    const float inv1 = 1.f / l1;

    float* c0 = ctx + ((size_t)b * SEQ + rowg0) * HID + (size_t)h * HDIM;
    float* c1 = ctx + ((size_t)b * SEQ + rowg1) * HID + (size_t)h * HDIM;
#pragma unroll
    for (int nt = 0; nt < 16; nt++) {
        const int col = nt * 8 + 2 * c;
        float2 w0, w1;
        w0.x = o[nt][0] * inv0; w0.y = o[nt][1] * inv0;
        w1.x = o[nt][2] * inv1; w1.y = o[nt][3] * inv1;
        *(float2*)(c0 + col) = w0;
        *(float2*)(c1 + col) = w1;
    }
}

// ===========================================================================
extern "C" void kernel_launch(void* const* d_in, const int* in_sizes, int n_in,
                              void* d_out, int out_size) {
    const float* x      = (const float*)d_in[0];
    const float* w_qkv  = (const float*)d_in[1];
    const float* b_qkv  = (const float*)d_in[2];
    const float* w_out  = (const float*)d_in[3];
    const float* b_out  = (const float*)d_in[4];
    float* out = (float*)d_out;

    float* qkv; cudaGetSymbolAddress((void**)&qkv, g_qkv);
    float* ctx; cudaGetSymbolAddress((void**)&ctx, g_ctx);

    cudaFuncSetAttribute(sgemm_tf32_kernel,
                         cudaFuncAttributeMaxDynamicSharedMemorySize, SMEM_GEMM_BYTES);
    cudaFuncSetAttribute(flash_attn_tc_kernel,
                         cudaFuncAttributeMaxDynamicSharedMemorySize, AT_SMEM_BYTES);

    // 1) QKV projection
    sgemm_tf32_kernel<<<dim3(K3 / 128, MROWS / 128), 256, SMEM_GEMM_BYTES>>>(
        x, w_qkv, b_qkv, qkv, K3, HID);

    // 2) pre-truncate qkv to tf32 (rna) in place -> no CVT in attention loop
    const int n4 = (MROWS * K3) / 4;
    tf32_round_kernel<<<n4 / 256, 256>>>((float4*)qkv, n4);

    // 3) tensor-core causal flash attention
    flash_attn_tc_kernel<<<dim3(SEQ / 128, NHEAD, BATCH), 256, AT_SMEM_BYTES>>>(qkv, ctx);

    // 4) output projection
    sgemm_tf32_kernel<<<dim3(HID / 128, MROWS / 128), 256, SMEM_GEMM_BYTES>>>(
        ctx, w_out, b_out, out, HID, HID);
}

// round 5
// speedup vs baseline: 3.7387x; 1.1088x over previous
#include <cuda_runtime.h>

// Problem constants
#define BATCH 2
#define SEQ   2048
#define HID   2048
#define NHEAD 16
#define HDIM  128
#define MROWS (BATCH * SEQ)   // 4096
#define K3    (3 * HID)       // 6144

// Scratch (allocation-free rule: __device__ globals)
__device__ float g_qkv[(size_t)MROWS * K3];   // [4096, 6144]
__device__ float g_ctx[(size_t)MROWS * HID];  // [4096, 2048]
__device__ float g_x  [(size_t)MROWS * HID];  // tf32-truncated x
__device__ float g_wq [(size_t)HID * K3];     // tf32-truncated w_qkv
__device__ float g_wo [(size_t)HID * HID];    // tf32-truncated w_out

__device__ __forceinline__ unsigned f2tf(float x) {
    unsigned u;
    asm("cvt.rna.tf32.f32 %0, %1;" : "=r"(u) : "f"(x));
    return u;
}

__device__ __forceinline__ void mma_tf32(float* d, const unsigned* a, const unsigned* b) {
    asm volatile(
        "mma.sync.aligned.m16n8k8.row.col.f32.tf32.tf32.f32 "
        "{%0,%1,%2,%3},{%4,%5,%6,%7},{%8,%9},{%0,%1,%2,%3};"
        : "+f"(d[0]), "+f"(d[1]), "+f"(d[2]), "+f"(d[3])
        : "r"(a[0]), "r"(a[1]), "r"(a[2]), "r"(a[3]), "r"(b[0]), "r"(b[1]));
}

__device__ __forceinline__ void cp16(unsigned dst, const void* src) {
    asm volatile("cp.async.cg.shared.global [%0], [%1], 16;\n" :: "r"(dst), "l"(src));
}

// ===========================================================================
// tf32 truncating copy (inputs -> scratch), run once per launch
// ===========================================================================
__global__ void trunc_copy_kernel(const float4* __restrict__ src,
                                  float4* __restrict__ dst, int n4) {
    int i = blockIdx.x * blockDim.x + threadIdx.x;
    if (i < n4) {
        float4 v = src[i];
        v.x = __uint_as_float(f2tf(v.x));
        v.y = __uint_as_float(f2tf(v.y));
        v.z = __uint_as_float(f2tf(v.z));
        v.w = __uint_as_float(f2tf(v.w));
        dst[i] = v;
    }
}

// ===========================================================================
// tf32 tensor-core SGEMM: C = A @ B + bias. Inputs already tf32-truncated,
// so the mainloop is pure LDS + MMA (zero CVT). TRUNC_OUT truncates the
// epilogue stores (for tensors that feed later tf32 stages).
// ===========================================================================
#define A_STAGE_W 4096
#define B_BASE_W  8192
#define B_STAGE_W 4224
#define BSTR      132
#define SMEM_GEMM_BYTES ((B_BASE_W + 2 * B_STAGE_W) * 4)   // 66560

template <bool TRUNC_OUT>
__global__ __launch_bounds__(256)
void sgemm_tf32_kernel(const float* __restrict__ A, const float* __restrict__ Bw,
                       const float* __restrict__ bias, float* __restrict__ C,
                       int N, int K) {
    extern __shared__ float sm[];
    const int tid = threadIdx.x;
    const int lane = tid & 31;
    const int warp = tid >> 5;
    const int wm = warp & 1;
    const int wn = warp >> 1;
    const int bm = blockIdx.y * 128;
    const int bn = blockIdx.x * 128;

    const int g = lane >> 2;
    const int c = lane & 3;
    const int swz = (g & 3) * 8;

    const int am = tid >> 3;
    const int aj = (tid & 7) * 4;
    const int bk = tid >> 3;
    const int bnn = (tid & 7) * 4;

    unsigned smu;
    { unsigned long long p = __cvta_generic_to_shared(sm); smu = (unsigned)p; }
    const unsigned aDst = smu + (unsigned)(am * 32 + (aj ^ ((am & 3) * 8))) * 4;
    const unsigned bDst = smu + (unsigned)(B_BASE_W + bk * BSTR + bnn) * 4;

    const float* aSrcBase = A + (size_t)(bm + am) * K + aj;
    const float* bSrcBase = Bw + (size_t)bk * N + bn + bnn;

    float acc[4][4][4];
#pragma unroll
    for (int mt = 0; mt < 4; mt++)
#pragma unroll
        for (int nt = 0; nt < 4; nt++)
#pragma unroll
            for (int r = 0; r < 4; r++) acc[mt][nt][r] = 0.f;

    const int T = K / 32;

    {
#pragma unroll
        for (int r = 0; r < 4; r++) {
            cp16(aDst + (unsigned)(r * 32 * 32) * 4, aSrcBase + (size_t)(r * 32) * K);
            cp16(bDst + (unsigned)(r * 32) * 4, bSrcBase + r * 32);
        }
        asm volatile("cp.async.commit_group;\n");
    }

    for (int i = 0; i < T; i++) {
        if (i + 1 < T) {
            const int ns = (i + 1) & 1;
            const float* as = aSrcBase + (i + 1) * 32;
            const float* bs = bSrcBase + (size_t)((i + 1) * 32) * N;
            const unsigned ad = aDst + (unsigned)(ns * A_STAGE_W) * 4;
            const unsigned bd = bDst + (unsigned)(ns * B_STAGE_W) * 4;
#pragma unroll
            for (int r = 0; r < 4; r++) {
                cp16(ad + (unsigned)(r * 32 * 32) * 4, as + (size_t)(r * 32) * K);
                cp16(bd + (unsigned)(r * 32) * 4, bs + r * 32);
            }
        }
        asm volatile("cp.async.commit_group;\n");
        asm volatile("cp.async.wait_group 1;\n");
        __syncthreads();

        const int st = i & 1;
        const float* As = sm + st * A_STAGE_W;
        const float* Bs = sm + B_BASE_W + st * B_STAGE_W;

#pragma unroll
        for (int s = 0; s < 4; s++) {
            const int kof = (8 * s + 2 * c) ^ swz;
            unsigned av[4][4];
#pragma unroll
            for (int mt = 0; mt < 4; mt++) {
                const float* pa = As + (wm * 64 + mt * 16 + g) * 32 + kof;
                float2 f0 = *(const float2*)pa;
                float2 f1 = *(const float2*)(pa + 8 * 32);
                av[mt][0] = __float_as_uint(f0.x);
                av[mt][2] = __float_as_uint(f0.y);
                av[mt][1] = __float_as_uint(f1.x);
                av[mt][3] = __float_as_uint(f1.y);
            }
            unsigned bv[4][2];
            const float* pbBase = Bs + (8 * s + 2 * c) * BSTR + wn * 32 + g;
#pragma unroll
            for (int nt = 0; nt < 4; nt++) {
                const float* pb = pbBase + nt * 8;
                bv[nt][0] = __float_as_uint(pb[0]);
                bv[nt][1] = __float_as_uint(pb[BSTR]);
            }
#pragma unroll
            for (int mt = 0; mt < 4; mt++)
#pragma unroll
                for (int nt = 0; nt < 4; nt++)
                    mma_tf32(acc[mt][nt], av[mt], bv[nt]);
        }
        __syncthreads();
    }

#pragma unroll
    for (int mt = 0; mt < 4; mt++) {
        const int row = bm + wm * 64 + mt * 16 + g;
#pragma unroll
        for (int nt = 0; nt < 4; nt++) {
            const int col = bn + wn * 32 + nt * 8 + 2 * c;
            const float b0 = __ldg(&bias[col]);
            const float b1 = __ldg(&bias[col + 1]);
            float v00 = acc[mt][nt][0] + b0, v01 = acc[mt][nt][1] + b1;
            float v10 = acc[mt][nt][2] + b0, v11 = acc[mt][nt][3] + b1;
            if (TRUNC_OUT) {
                v00 = __uint_as_float(f2tf(v00));
                v01 = __uint_as_float(f2tf(v01));
                v10 = __uint_as_float(f2tf(v10));
                v11 = __uint_as_float(f2tf(v11));
            }
            float2 o0 = {v00, v01}, o1 = {v10, v11};
            *(float2*)(C + (size_t)row * N + col) = o0;
            *(float2*)(C + (size_t)(row + 8) * N + col) = o1;
        }
    }
}

// ===========================================================================
// Tensor-core causal flash attention (tf32 mma). qkv already tf32 bits.
// BQ=128, BKV=64, 8 warps x 16 q-rows. S fragments reused as P A-operands.
// Epilogue truncates ctx to tf32 so the out-projection mainloop is CVT-free.
// ===========================================================================
#define K_STW 8192
#define V_STW 8448
#define V_BASE_W 16384
#define AT_SMEM_BYTES ((V_BASE_W + 2 * V_STW) * 4)   // 133120

__global__ __launch_bounds__(256, 1)
void flash_attn_tc_kernel(const float* __restrict__ qkv, float* __restrict__ ctx) {
    extern __shared__ float sm[];
    const int tid = threadIdx.x;
    const int lane = tid & 31;
    const int wid = tid >> 5;
    const int g = lane >> 2;
    const int c = lane & 3;
    const int qt = 15 - blockIdx.x;
    const int h = blockIdx.y;
    const int b = blockIdx.z;
    const int q0 = qt * 128;
    const float scale = 0.08838834764831845f;

    const float* base = qkv + ((size_t)b * SEQ) * K3 + (size_t)h * (3 * HDIM);

    unsigned smu;
    { unsigned long long p = __cvta_generic_to_shared(sm); smu = (unsigned)p; }

    const int ntiles = 2 * qt + 2;

    auto issue_tile = [&](int j, int st) {
        const float* kvb = base + (size_t)(j * 64) * K3;
#pragma unroll
        for (int r = 0; r < 8; r++) {
            int chunk = tid + 256 * r;
            int row = chunk >> 5;
            int cw = (chunk & 31) * 4;
            const float* src = kvb + (size_t)row * K3 + cw;
            unsigned kd = smu + (unsigned)(st * K_STW + row * 128 + (cw ^ ((row & 3) * 8))) * 4;
            unsigned vd = smu + (unsigned)(V_BASE_W + st * V_STW + row * 132 + cw) * 4;
            cp16(kd, src + HDIM);
            cp16(vd, src + 2 * HDIM);
        }
    };

    issue_tile(0, 0);
    asm volatile("cp.async.commit_group;\n");

    unsigned qf[16][4];
    {
        const float* qrow = base + (size_t)(q0 + wid * 16 + g) * K3;
        const float* qrow8 = qrow + 8 * (size_t)K3;
#pragma unroll
        for (int s = 0; s < 16; s++) {
            float2 f0 = *(const float2*)(qrow + 8 * s + 2 * c);
            float2 f1 = *(const float2*)(qrow8 + 8 * s + 2 * c);
            qf[s][0] = __float_as_uint(f0.x);
            qf[s][2] = __float_as_uint(f0.y);
            qf[s][1] = __float_as_uint(f1.x);
            qf[s][3] = __float_as_uint(f1.y);
        }
    }

    float o[16][4];
#pragma unroll
    for (int nt = 0; nt < 16; nt++)
#pragma unroll
        for (int r = 0; r < 4; r++) o[nt][r] = 0.f;
    float m0 = -1e30f, m1 = -1e30f, l0 = 0.f, l1 = 0.f;

    const int rowg0 = q0 + wid * 16 + g;
    const int rowg1 = rowg0 + 8;

    for (int j = 0; j < ntiles; j++) {
        if (j + 1 < ntiles) issue_tile(j + 1, (j + 1) & 1);
        asm volatile("cp.async.commit_group;\n");
        asm volatile("cp.async.wait_group 1;\n");
        __syncthreads();

        const int st = j & 1;
        const float* Ks = sm + st * K_STW;
        const float* Vs = sm + V_BASE_W + st * V_STW;

        float sv[8][4];
#pragma unroll
        for (int nt = 0; nt < 8; nt++)
#pragma unroll
            for (int r = 0; r < 4; r++) sv[nt][r] = 0.f;

#pragma unroll
        for (int s = 0; s < 16; s++) {
            const int kof = (8 * s + 2 * c) ^ ((g & 3) * 8);
#pragma unroll
            for (int nt = 0; nt < 8; nt++) {
                float2 kf = *(const float2*)(Ks + (nt * 8 + g) * 128 + kof);
                unsigned bv[2] = {__float_as_uint(kf.x), __float_as_uint(kf.y)};
                mma_tf32(sv[nt], qf[s], bv);
            }
        }

#pragma unroll
        for (int nt = 0; nt < 8; nt++)
#pragma unroll
            for (int r = 0; r < 4; r++) sv[nt][r] *= scale;

        if (j >= 2 * qt) {
            const int kv0 = j * 64;
#pragma unroll
            for (int nt = 0; nt < 8; nt++) {
                const int col = kv0 + nt * 8 + 2 * c;
                if (col     > rowg0) sv[nt][0] = -1e30f;
                if (col + 1 > rowg0) sv[nt][1] = -1e30f;
                if (col     > rowg1) sv[nt][2] = -1e30f;
                if (col + 1 > rowg1) sv[nt][3] = -1e30f;
            }
        }

        float mx0 = -1e30f, mx1 = -1e30f;
#pragma unroll
        for (int nt = 0; nt < 8; nt++) {
            mx0 = fmaxf(mx0, fmaxf(sv[nt][0], sv[nt][1]));
            mx1 = fmaxf(mx1, fmaxf(sv[nt][2], sv[nt][3]));
        }
        mx0 = fmaxf(mx0, __shfl_xor_sync(0xffffffffu, mx0, 1));
        mx0 = fmaxf(mx0, __shfl_xor_sync(0xffffffffu, mx0, 2));
        mx1 = fmaxf(mx1, __shfl_xor_sync(0xffffffffu, mx1, 1));
        mx1 = fmaxf(mx1, __shfl_xor_sync(0xffffffffu, mx1, 2));

        const float mn0 = fmaxf(m0, mx0);
        const float mn1 = fmaxf(m1, mx1);
        const float a0 = __expf(m0 - mn0);
        const float a1 = __expf(m1 - mn1);
        m0 = mn0; m1 = mn1;

        float l0a = 0.f, l1a = 0.f;
        unsigned pf[8][4];
#pragma unroll
        for (int nt = 0; nt < 8; nt++) {
            float p0 = __expf(sv[nt][0] - mn0);
            float p1 = __expf(sv[nt][1] - mn0);
            float p2 = __expf(sv[nt][2] - mn1);
            float p3 = __expf(sv[nt][3] - mn1);
            l0a += p0 + p1;
            l1a += p2 + p3;
            pf[nt][0] = f2tf(p0);
            pf[nt][1] = f2tf(p2);
            pf[nt][2] = f2tf(p1);
            pf[nt][3] = f2tf(p3);
        }
        l0 = l0 * a0 + l0a;
        l1 = l1 * a1 + l1a;

#pragma unroll
        for (int nt = 0; nt < 16; nt++) {
            o[nt][0] *= a0; o[nt][1] *= a0;
            o[nt][2] *= a1; o[nt][3] *= a1;
        }

#pragma unroll
        for (int s = 0; s < 8; s++) {
            const float* vrow = Vs + (8 * s + 2 * c) * 132 + g;
#pragma unroll
            for (int nt = 0; nt < 16; nt++) {
                unsigned bv[2] = {__float_as_uint(vrow[nt * 8]),
                                  __float_as_uint(vrow[nt * 8 + 132])};
                mma_tf32(o[nt], pf[s], bv);
            }
        }
        __syncthreads();
    }

    l0 += __shfl_xor_sync(0xffffffffu, l0, 1);
    l0 += __shfl_xor_sync(0xffffffffu, l0, 2);
    l1 += __shfl_xor_sync(0xffffffffu, l1, 1);
    l1 += __shfl_xor_sync(0xffffffffu, l1, 2);
    const float inv0 = 1.f / l0;
    const float inv1 = 1.f / l1;

    float* c0 = ctx + ((size_t)b * SEQ + rowg0) * HID + (size_t)h * HDIM;
    float* c1 = ctx + ((size_t)b * SEQ + rowg1) * HID + (size_t)h * HDIM;
#pragma unroll
    for (int nt = 0; nt < 16; nt++) {
        const int col = nt * 8 + 2 * c;
        float2 w0, w1;
        w0.x = __uint_as_float(f2tf(o[nt][0] * inv0));
        w0.y = __uint_as_float(f2tf(o[nt][1] * inv0));
        w1.x = __uint_as_float(f2tf(o[nt][2] * inv1));
        w1.y = __uint_as_float(f2tf(o[nt][3] * inv1));
        *(float2*)(c0 + col) = w0;
        *(float2*)(c1 + col) = w1;
    }
}

// ===========================================================================
extern "C" void kernel_launch(void* const* d_in, const int* in_sizes, int n_in,
                              void* d_out, int out_size) {
    const float* x      = (const float*)d_in[0];
    const float* w_qkv  = (const float*)d_in[1];
    const float* b_qkv  = (const float*)d_in[2];
    const float* w_out  = (const float*)d_in[3];
    const float* b_out  = (const float*)d_in[4];
    float* out = (float*)d_out;

    float* qkv; cudaGetSymbolAddress((void**)&qkv, g_qkv);
    float* ctx; cudaGetSymbolAddress((void**)&ctx, g_ctx);
    float* xt;  cudaGetSymbolAddress((void**)&xt,  g_x);
    float* wq;  cudaGetSymbolAddress((void**)&wq,  g_wq);
    float* wo;  cudaGetSymbolAddress((void**)&wo,  g_wo);

    cudaFuncSetAttribute(sgemm_tf32_kernel<true>,
                         cudaFuncAttributeMaxDynamicSharedMemorySize, SMEM_GEMM_BYTES);
    cudaFuncSetAttribute(sgemm_tf32_kernel<false>,
                         cudaFuncAttributeMaxDynamicSharedMemorySize, SMEM_GEMM_BYTES);
    cudaFuncSetAttribute(flash_attn_tc_kernel,
                         cudaFuncAttributeMaxDynamicSharedMemorySize, AT_SMEM_BYTES);

    // 0) truncate inputs to tf32 once -> mainloops are CVT-free
    trunc_copy_kernel<<<(MROWS * HID / 4) / 256, 256>>>((const float4*)x, (float4*)xt, MROWS * HID / 4);
    trunc_copy_kernel<<<(HID * K3 / 4) / 256, 256>>>((const float4*)w_qkv, (float4*)wq, HID * K3 / 4);
    trunc_copy_kernel<<<(HID * HID / 4) / 256, 256>>>((const float4*)w_out, (float4*)wo, HID * HID / 4);

    // 1) QKV projection (epilogue truncates -> qkv already tf32 bits)
    sgemm_tf32_kernel<true><<<dim3(K3 / 128, MROWS / 128), 256, SMEM_GEMM_BYTES>>>(
        xt, wq, b_qkv, qkv, K3, HID);

    // 2) tensor-core causal flash attention (epilogue truncates ctx)
    flash_attn_tc_kernel<<<dim3(SEQ / 128, NHEAD, BATCH), 256, AT_SMEM_BYTES>>>(qkv, ctx);

    // 3) output projection (fp32 out, no truncation)
    sgemm_tf32_kernel<false><<<dim3(HID / 128, MROWS / 128), 256, SMEM_GEMM_BYTES>>>(
        ctx, wo, b_out, out, HID, HID);
}